// round 9
// baseline (speedup 1.0000x reference)
#include <cuda_runtime.h>

#define B_  32
#define S_  64
#define T_  32
#define H_  512
#define V_  32000
#define K3  1536
#define NLT 250   // logits tiles (128 v-rows each)

typedef unsigned long long ull;

// ---------------- device scratch ----------------
__device__ float g_Ukeys[B_ * S_ * H_];
__device__ float g_query[2][1024 * B_];   // [(l*512+h)][b], double buffered
__device__ float g_ctxT[512 * B_];        // context [h][b]
__device__ float g_qpT[4][B_ * H_];       // q partials transposed [b][h]
__device__ float g_gh0p[2][K3 * B_];
__device__ float g_gh1p[2][K3 * B_];
__device__ float g_gi0p[4][K3 * B_];
__device__ float g_gi1p[2][K3 * B_];
__device__ float g_logits[B_ * V_];       // [b][v]
__device__ float g_pm[B_ * NLT];
__device__ float g_ps[B_ * NLT];
__device__ int   g_pi[B_ * NLT];
__device__ int   g_tok[B_];

// ---------------- helpers ----------------
__device__ __forceinline__ ull pk2(float a, float b) {
    ull r; asm("mov.b64 %0, {%1,%2};" : "=l"(r) : "f"(a), "f"(b)); return r;
}
__device__ __forceinline__ ull fma2(ull a, ull b, ull c) {
    ull d; asm("fma.rn.f32x2 %0, %1, %2, %3;" : "=l"(d) : "l"(a), "l"(b), "l"(c)); return d;
}
__device__ __forceinline__ void upk(ull v, float& lo, float& hi) {
    asm("mov.b64 {%0,%1}, %2;" : "=f"(lo), "=f"(hi) : "l"(v));
}
__device__ __forceinline__ float tanh_ap(float x) {
    float y; asm("tanh.approx.f32 %0, %1;" : "=f"(y) : "f"(x)); return y;
}
__device__ __forceinline__ float sig_fast(float x) {
    return __fdividef(1.f, 1.f + __expf(-x));
}

// ---------------- staging ----------------
__device__ __forceinline__ void stage256(const float* __restrict__ X, float* Xs) {
    int tid = threadIdx.x;
    const float4* s = (const float4*)X;
    float4* d = (float4*)Xs;
    #pragma unroll
    for (int i = 0; i < 8; i++) d[tid + 256 * i] = s[tid + 256 * i];
}
__device__ __forceinline__ void stage128(const float* __restrict__ X, float* Xs) {
    int tid = threadIdx.x;
    const float4* s = (const float4*)X;
    float4* d = (float4*)Xs;
    #pragma unroll
    for (int i = 0; i < 16; i++) d[tid + 128 * i] = s[tid + 128 * i];
}

// ---------------- GEMM tile: 64 m x 32 b x 256 k, 256 threads ----------------
__device__ __forceinline__ void gemm64(
    const float* __restrict__ W, int ldW,
    float* __restrict__ C, int m0, const float* Xs)
{
    int tid = threadIdx.x;
    int bt = tid & 3, mtt = tid >> 2;
    int b0 = bt * 8;
    const float* wr = W + (size_t)(m0 + mtt) * ldW;
    ull acc[4] = {0ULL, 0ULL, 0ULL, 0ULL};
    for (int kk = 0; kk < 256; kk += 4) {
        float4 w = *(const float4*)(wr + kk);
        float wf[4] = {w.x, w.y, w.z, w.w};
        #pragma unroll
        for (int c = 0; c < 4; c++) {
            ull wd = pk2(wf[c], wf[c]);
            #pragma unroll
            for (int j = 0; j < 4; j++)
                acc[j] = fma2(wd, *(const ull*)&Xs[(kk + c) * 32 + b0 + 2 * j], acc[j]);
        }
    }
    #pragma unroll
    for (int j = 0; j < 4; j++)
        *(ull*)&C[(size_t)(m0 + mtt) * 32 + b0 + 2 * j] = acc[j];
}

// transposed-store variant (for q): C[b*512 + m]
__device__ __forceinline__ void gemm64T(
    const float* __restrict__ W, int ldW,
    float* __restrict__ C, int m0, const float* Xs)
{
    int tid = threadIdx.x;
    int bt = tid & 3, mtt = tid >> 2;
    int b0 = bt * 8;
    const float* wr = W + (size_t)(m0 + mtt) * ldW;
    ull acc[4] = {0ULL, 0ULL, 0ULL, 0ULL};
    for (int kk = 0; kk < 256; kk += 4) {
        float4 w = *(const float4*)(wr + kk);
        float wf[4] = {w.x, w.y, w.z, w.w};
        #pragma unroll
        for (int c = 0; c < 4; c++) {
            ull wd = pk2(wf[c], wf[c]);
            #pragma unroll
            for (int j = 0; j < 4; j++)
                acc[j] = fma2(wd, *(const ull*)&Xs[(kk + c) * 32 + b0 + 2 * j], acc[j]);
        }
    }
    int m = m0 + mtt;
    #pragma unroll
    for (int j = 0; j < 4; j++) {
        float lo, hi; upk(acc[j], lo, hi);
        C[(size_t)(b0 + 2 * j) * 512 + m]     = lo;
        C[(size_t)(b0 + 2 * j + 1) * 512 + m] = hi;
    }
}

// ---------------- GEMM tile: 128 m x 32 b x 256 k, 128 threads ----------------
__device__ __forceinline__ void gemm_core(
    const float* __restrict__ W, int ldW,
    float* __restrict__ C, int m0, const float* Xs)
{
    int tid = threadIdx.x;
    int bt = tid & 3, mt = tid >> 2;
    int b0 = bt * 8;
    const float* wr0 = W + (size_t)(m0 + mt) * ldW;

    ull acc[4][4];
    #pragma unroll
    for (int i = 0; i < 4; i++)
        #pragma unroll
        for (int j = 0; j < 4; j++) acc[i][j] = 0ULL;

    for (int kk = 0; kk < 256; kk += 4) {
        float4 w[4];
        #pragma unroll
        for (int i = 0; i < 4; i++)
            w[i] = *(const float4*)(wr0 + (size_t)i * 32 * ldW + kk);
        #pragma unroll
        for (int c = 0; c < 4; c++) {
            ull xp[4];
            #pragma unroll
            for (int j = 0; j < 4; j++)
                xp[j] = *(const ull*)&Xs[(kk + c) * 32 + b0 + 2 * j];
            #pragma unroll
            for (int i = 0; i < 4; i++) {
                const float* wf = reinterpret_cast<const float*>(&w[i]);
                ull wd = pk2(wf[c], wf[c]);
                #pragma unroll
                for (int j = 0; j < 4; j++) acc[i][j] = fma2(wd, xp[j], acc[i][j]);
            }
        }
    }
    #pragma unroll
    for (int i = 0; i < 4; i++)
        #pragma unroll
        for (int j = 0; j < 4; j++)
            *(ull*)&C[(size_t)(m0 + mt + i * 32) * 32 + b0 + 2 * j] = acc[i][j];
}

// ---------------- smwrite unit ----------------
__device__ __forceinline__ void smwrite_unit(int u, float* __restrict__ lp, int tprev,
                                             float* rm, float* rs, int* ri)
{
    int tid = threadIdx.x;
    int b = u >> 2, c = u & 3;
    float m = -1e30f, s = 0.f; int id = 0x7fffffff;
    if (tid < NLT) { m = g_pm[b * NLT + tid]; s = g_ps[b * NLT + tid]; id = g_pi[b * NLT + tid]; }
    rm[tid] = m; rs[tid] = s; ri[tid] = id;
    __syncthreads();
    for (int o = 128; o; o >>= 1) {
        if (tid < o) {
            float mq = rm[tid + o], sq = rs[tid + o];
            int iq = ri[tid + o];
            float mm = rm[tid];
            if (mq > mm || (mq == mm && iq < ri[tid])) {
                rs[tid] = rs[tid] * __expf(mm - mq) + sq; rm[tid] = mq; ri[tid] = iq;
            } else {
                rs[tid] += sq * __expf(mq - mm);
            }
        }
        __syncthreads();
    }
    float lse = logf(rs[0]) + rm[0];
    if (c == 0 && tid == 0) g_tok[b] = ri[0];
    const float* lg = g_logits + (size_t)b * V_;
    float* o = lp + ((size_t)b * T_ + tprev) * V_;
    for (int v = c * 8000 + tid; v < (c + 1) * 8000; v += 256)
        o[v] = lg[v] - lse;
}

// ---------------- init ----------------
__global__ void k_init(const float* __restrict__ ehid) {
    int idx = blockIdx.x * 256 + threadIdx.x;   // 32768
    int row = idx >> 5, b = idx & 31;
    int l = row >> 9, h = row & 511;
    g_query[0][row * 32 + b] = ehid[((size_t)l * 32 + b) * 512 + h];
    if (idx < B_) g_tok[idx] = 1;  // BOS
}

// ---------------- Ukeys = enc @ Ua^T + bua ----------------
__global__ __launch_bounds__(256) void k_ukeys(
    const float* __restrict__ enc, const float* __restrict__ Ua,
    const float* __restrict__ bua)
{
    __shared__ float es[8 * 512];
    int row0 = blockIdx.x * 8;   // grid 256
    int tid = threadIdx.x;
    {
        const float4* src = (const float4*)(enc + (size_t)row0 * 512);
        #pragma unroll
        for (int i = 0; i < 4; i++) ((float4*)es)[tid + 256 * i] = src[tid + 256 * i];
    }
    __syncthreads();
    int h = tid;
    float acc0[8], acc1[8];
    #pragma unroll
    for (int r = 0; r < 8; r++) { acc0[r] = 0.f; acc1[r] = 0.f; }
    const float* u0 = Ua + (size_t)h * 512;
    const float* u1 = Ua + (size_t)(h + 256) * 512;
    for (int k = 0; k < 512; k++) {
        float w0 = u0[k], w1 = u1[k];
        #pragma unroll
        for (int r = 0; r < 8; r++) {
            float x = es[r * 512 + k];
            acc0[r] += w0 * x; acc1[r] += w1 * x;
        }
    }
    float bb0 = bua[h], bb1 = bua[h + 256];
    #pragma unroll
    for (int r = 0; r < 8; r++) {
        g_Ukeys[(size_t)(row0 + r) * 512 + h]       = acc0[r] + bb0;
        g_Ukeys[(size_t)(row0 + r) * 512 + h + 256] = acc1[r] + bb1;
    }
}

// ---------------- N1: pre3 GEMMs (blocks 0..127) + smwrite(t-1) (blocks 128..255) ----------------
__global__ __launch_bounds__(256) void k_pre3sw(
    const float* __restrict__ Wa, const float* __restrict__ Whh0,
    const float* __restrict__ Whh1, float* __restrict__ lp, int t)
{
    __shared__ float Xs[8192];
    int blk = blockIdx.x;
    int par = t & 1;
    const float* hprev = (const float*)g_query[par];
    if (blk < 32) {                 // q: 8 mt x 4 ks, transposed store
        int mt = blk >> 2, ks = blk & 3;
        stage256(hprev + ks * 8192, Xs);
        __syncthreads();
        gemm64T(Wa + ks * 256, 1024, g_qpT[ks], mt * 64, Xs);
    } else if (blk < 80) {          // gh0: 24 mt x 2 ks
        int tt = blk - 32; int mt = tt >> 1, ks = tt & 1;
        stage256(hprev + ks * 8192, Xs);
        __syncthreads();
        gemm64(Whh0 + ks * 256, 512, g_gh0p[ks], mt * 64, Xs);
    } else if (blk < 128) {         // gh1: 24 mt x 2 ks
        int tt = blk - 80; int mt = tt >> 1, ks = tt & 1;
        stage256(hprev + 512 * 32 + ks * 8192, Xs);
        __syncthreads();
        gemm64(Whh1 + ks * 256, 512, g_gh1p[ks], mt * 64, Xs);
    } else if (t > 0) {             // smwrite for step t-1
        smwrite_unit(blk - 128, lp, t - 1, Xs, Xs + 256, (int*)(Xs + 512));
    }
}

// ---------------- N2: attention fused (32 blocks x 512 threads), interleaved scores ----------------
__global__ __launch_bounds__(512) void k_attn(
    const float* __restrict__ enc,
    const float* __restrict__ ba, const float* __restrict__ Va,
    const float* __restrict__ bva,
    float* __restrict__ attn, int t)
{
    __shared__ float qs[512], vas[512], sc[64], ws[64];
    int b = blockIdx.x, tid = threadIdx.x;
    {
        int i = tid;
        qs[i] = g_qpT[0][b * 512 + i] + g_qpT[1][b * 512 + i]
              + g_qpT[2][b * 512 + i] + g_qpT[3][b * 512 + i] + ba[i];
        vas[i] = Va[i];
    }
    __syncthreads();
    int w = tid >> 5, lane = tid & 31;
    {
        // 4 s-rows per warp, interleaved for MLP
        int s0 = w * 4;
        const float* uk0 = g_Ukeys + ((size_t)(b * 64 + s0 + 0)) * 512;
        const float* uk1 = g_Ukeys + ((size_t)(b * 64 + s0 + 1)) * 512;
        const float* uk2 = g_Ukeys + ((size_t)(b * 64 + s0 + 2)) * 512;
        const float* uk3 = g_Ukeys + ((size_t)(b * 64 + s0 + 3)) * 512;
        float a0 = 0.f, a1 = 0.f, a2 = 0.f, a3 = 0.f;
        #pragma unroll 4
        for (int i = 0; i < 16; i++) {
            int h = lane + 32 * i;
            float u0 = uk0[h], u1 = uk1[h], u2 = uk2[h], u3 = uk3[h];
            float q = qs[h], va = vas[h];
            a0 += va * tanh_ap(q + u0);
            a1 += va * tanh_ap(q + u1);
            a2 += va * tanh_ap(q + u2);
            a3 += va * tanh_ap(q + u3);
        }
        #pragma unroll
        for (int o = 16; o; o >>= 1) {
            a0 += __shfl_xor_sync(0xffffffffu, a0, o);
            a1 += __shfl_xor_sync(0xffffffffu, a1, o);
            a2 += __shfl_xor_sync(0xffffffffu, a2, o);
            a3 += __shfl_xor_sync(0xffffffffu, a3, o);
        }
        if (lane == 0) {
            float bv = bva[0];
            sc[s0 + 0] = a0 + bv; sc[s0 + 1] = a1 + bv;
            sc[s0 + 2] = a2 + bv; sc[s0 + 3] = a3 + bv;
        }
    }
    __syncthreads();
    if (tid < 32) {
        float v0 = sc[tid], v1 = sc[32 + tid];
        float m = fmaxf(v0, v1);
        #pragma unroll
        for (int o = 16; o; o >>= 1) m = fmaxf(m, __shfl_xor_sync(0xffffffffu, m, o));
        float e0 = __expf(v0 - m), e1 = __expf(v1 - m);
        float s = e0 + e1;
        #pragma unroll
        for (int o = 16; o; o >>= 1) s += __shfl_xor_sync(0xffffffffu, s, o);
        float inv = 1.f / s;
        ws[tid] = e0 * inv; ws[32 + tid] = e1 * inv;
    }
    __syncthreads();
    if (attn && tid < 64)
        attn[((size_t)b * T_ + t) * 64 + tid] = ws[tid];
    {
        int h = tid;
        float c = 0.f;
        const float* e = enc + ((size_t)b * 64) * 512 + h;
        #pragma unroll 8
        for (int s = 0; s < 64; s++) c += ws[s] * e[(size_t)s * 512];
        g_ctxT[h * 32 + b] = c;
    }
}

// ---------------- N3: gi0 = W0ih @ [emb(tok); ctx]  (96 blocks x 256) ----------------
__global__ __launch_bounds__(256) void k_gi0(
    const float* __restrict__ W0ih, const float* __restrict__ emb)
{
    __shared__ float Xs[8192];
    int blk = blockIdx.x, tid = threadIdx.x;
    int mt = blk >> 2, ks = blk & 3;
    if (ks < 2) {
        int b = tid & 31, seg = tid >> 5;   // 8 segs x 32 k
        int tok = g_tok[b];
        const float* er = emb + (size_t)tok * 512 + ks * 256 + seg * 32;
        #pragma unroll
        for (int i = 0; i < 8; i++) {
            float4 v = *(const float4*)(er + i * 4);
            int k = seg * 32 + i * 4;
            Xs[(k + 0) * 32 + b] = v.x; Xs[(k + 1) * 32 + b] = v.y;
            Xs[(k + 2) * 32 + b] = v.z; Xs[(k + 3) * 32 + b] = v.w;
        }
    } else {
        stage256(g_ctxT + (ks - 2) * 8192, Xs);
    }
    __syncthreads();
    gemm64(W0ih + ks * 256, 1024, g_gi0p[ks], mt * 64, Xs);
}

// ---------------- N4: comb0 (fast-math recompute) + gi1  (48 blocks x 256) ----------------
__global__ __launch_bounds__(256) void k_gi1c0(
    const float* __restrict__ W1ih,
    const float* __restrict__ b0ih, const float* __restrict__ b0hh, int par)
{
    __shared__ float Xs[8192];
    int blk = blockIdx.x, tid = threadIdx.x;
    int mt = blk >> 1, ks = blk & 1;
    // compute h0 for rows [ks*256, +256) x 32 b into Xs ([k][b])
    #pragma unroll 4
    for (int r = 0; r < 32; r++) {
        int e = tid + 256 * r;          // 8192 elems
        int b = e & 31, jl = e >> 5;
        int j = ks * 256 + jl;
        int o_r = j * 32 + b, o_z = (j + 512) * 32 + b, o_n = (j + 1024) * 32 + b;
        float gir  = g_gi0p[0][o_r] + g_gi0p[1][o_r] + g_gi0p[2][o_r] + g_gi0p[3][o_r] + b0ih[j];
        float giz  = g_gi0p[0][o_z] + g_gi0p[1][o_z] + g_gi0p[2][o_z] + g_gi0p[3][o_z] + b0ih[j + 512];
        float gin_ = g_gi0p[0][o_n] + g_gi0p[1][o_n] + g_gi0p[2][o_n] + g_gi0p[3][o_n] + b0ih[j + 1024];
        float ghr = g_gh0p[0][o_r] + g_gh0p[1][o_r] + b0hh[j];
        float ghz = g_gh0p[0][o_z] + g_gh0p[1][o_z] + b0hh[j + 512];
        float ghn = g_gh0p[0][o_n] + g_gh0p[1][o_n] + b0hh[j + 1024];
        float hp = g_query[par][j * 32 + b];
        float rr = sig_fast(gir + ghr);
        float zz = sig_fast(giz + ghz);
        float nn = tanh_ap(gin_ + rr * ghn);
        float h0 = (1.f - zz) * nn + zz * hp;
        Xs[jl * 32 + b] = h0;
        if (blk < 2) g_query[par ^ 1][j * 32 + b] = h0;   // blocks 0,1 persist h0
    }
    __syncthreads();
    gemm64(W1ih + ks * 256, 512, g_gi1p[ks], mt * 64, Xs);
}

// ---------------- N5: comb1 (64 blocks x 256, precise) ----------------
__global__ __launch_bounds__(256) void k_comb1(
    int par, const float* __restrict__ bih, const float* __restrict__ bhh)
{
    int idx = blockIdx.x * 256 + threadIdx.x;   // 16384
    int j = idx >> 5, b = idx & 31;
    int o_r = j * 32 + b, o_z = (j + 512) * 32 + b, o_n = (j + 1024) * 32 + b;
    float gir  = g_gi1p[0][o_r] + g_gi1p[1][o_r] + bih[j];
    float giz  = g_gi1p[0][o_z] + g_gi1p[1][o_z] + bih[j + 512];
    float gin_ = g_gi1p[0][o_n] + g_gi1p[1][o_n] + bih[j + 1024];
    float ghr = g_gh1p[0][o_r] + g_gh1p[1][o_r] + bhh[j];
    float ghz = g_gh1p[0][o_z] + g_gh1p[1][o_z] + bhh[j + 512];
    float ghn = g_gh1p[0][o_n] + g_gh1p[1][o_n] + bhh[j + 1024];
    float hp = g_query[par][(512 + j) * 32 + b];
    float r = 1.f / (1.f + expf(-(gir + ghr)));
    float z = 1.f / (1.f + expf(-(giz + ghz)));
    float n = tanhf(gin_ + r * ghn);
    g_query[par ^ 1][(512 + j) * 32 + b] = (1.f - z) * n + z * hp;
}

// ---------------- N6: logits + softmax partials (250 blocks x 128) ----------------
__global__ __launch_bounds__(128) void k_logits(
    const float* __restrict__ outW, const float* __restrict__ outb, int parN)
{
    __shared__ float Xs[8192];
    int tid = threadIdx.x;
    int bt = tid & 3, mt = tid >> 2;
    int b0 = bt * 8;
    int v0 = blockIdx.x * 128;   // grid 250
    ull acc[4][4];
    #pragma unroll
    for (int i = 0; i < 4; i++)
        #pragma unroll
        for (int j = 0; j < 4; j++) acc[i][j] = 0ULL;

    const float* h1T = (const float*)g_query[parN] + 512 * 32;
    for (int ck = 0; ck < 2; ck++) {
        if (ck) __syncthreads();
        stage128(h1T + ck * 8192, Xs);
        __syncthreads();
        const float* wr0 = outW + (size_t)(v0 + mt) * 512 + ck * 256;
        for (int kk = 0; kk < 256; kk += 4) {
            float4 w[4];
            #pragma unroll
            for (int i = 0; i < 4; i++)
                w[i] = *(const float4*)(wr0 + (size_t)i * 32 * 512 + kk);
            #pragma unroll
            for (int c = 0; c < 4; c++) {
                ull xp[4];
                #pragma unroll
                for (int j = 0; j < 4; j++)
                    xp[j] = *(const ull*)&Xs[(kk + c) * 32 + b0 + 2 * j];
                #pragma unroll
                for (int i = 0; i < 4; i++) {
                    const float* wf = reinterpret_cast<const float*>(&w[i]);
                    ull wd = pk2(wf[c], wf[c]);
                    #pragma unroll
                    for (int j = 0; j < 4; j++) acc[i][j] = fma2(wd, xp[j], acc[i][j]);
                }
            }
        }
    }
    float lv[8][4];
    #pragma unroll
    for (int i = 0; i < 4; i++) {
        int v = v0 + mt + i * 32;
        float bb = outb[v];
        #pragma unroll
        for (int j = 0; j < 4; j++) {
            float lo, hi; upk(acc[i][j], lo, hi);
            lv[2 * j][i] = lo + bb; lv[2 * j + 1][i] = hi + bb;
            g_logits[(size_t)(b0 + 2 * j) * V_ + v]     = lo + bb;
            g_logits[(size_t)(b0 + 2 * j + 1) * V_ + v] = hi + bb;
        }
    }
    __syncthreads();
    float* sm_m = Xs;
    float* sm_s = Xs + 1024;
    int*   sm_i = (int*)(Xs + 2048);
    #pragma unroll
    for (int jj = 0; jj < 8; jj++) {
        int b = b0 + jj;
        float m = lv[jj][0]; int id = v0 + mt;
        #pragma unroll
        for (int i = 1; i < 4; i++) {
            float x = lv[jj][i];
            if (x > m) { m = x; id = v0 + mt + i * 32; }
        }
        float s = 0.f;
        #pragma unroll
        for (int i = 0; i < 4; i++) s += __expf(lv[jj][i] - m);
        sm_m[b * 32 + mt] = m; sm_s[b * 32 + mt] = s; sm_i[b * 32 + mt] = id;
    }
    __syncthreads();
    if (tid < 32) {
        int b = tid;
        float m = sm_m[b * 32], s = sm_s[b * 32];
        int id = sm_i[b * 32];
        for (int q = 1; q < 32; q++) {
            float mq = sm_m[b * 32 + q], sq = sm_s[b * 32 + q];
            int iq = sm_i[b * 32 + q];
            if (mq > m || (mq == m && iq < id)) {
                s = s * __expf(m - mq) + sq; m = mq; id = iq;
            } else {
                s += sq * __expf(mq - m);
            }
        }
        g_pm[b * NLT + blockIdx.x] = m;
        g_ps[b * NLT + blockIdx.x] = s;
        g_pi[b * NLT + blockIdx.x] = id;
    }
}

// ---------------- trailing: smwrite(31) + hidden out (128 blocks) ----------------
__global__ __launch_bounds__(256) void k_last(float* __restrict__ lp, float* __restrict__ hid)
{
    __shared__ float rm[256], rs[256];
    __shared__ int ri[256];
    smwrite_unit(blockIdx.x, lp, T_ - 1, rm, rs, ri);
    int idx = blockIdx.x * 256 + threadIdx.x;   // 32768
    int row = idx >> 5, b = idx & 31;
    int l = row >> 9, h = row & 511;
    if (hid) hid[((size_t)l * 32 + b) * 512 + h] = g_query[0][row * 32 + b];
}

// ---------------- launcher (single stream) ----------------
extern "C" void kernel_launch(void* const* d_in, const int* in_sizes, int n_in,
                              void* d_out, int out_size)
{
    const float* enc  = (const float*)d_in[0];
    const float* ehid = (const float*)d_in[1];
    const float* emb  = (const float*)d_in[3];
    const float* Wa   = (const float*)d_in[4];
    const float* ba   = (const float*)d_in[5];
    const float* Ua   = (const float*)d_in[6];
    const float* bua  = (const float*)d_in[7];
    const float* Va   = (const float*)d_in[8];
    const float* bva  = (const float*)d_in[9];
    const float* W0ih = (const float*)d_in[10];
    const float* W0hh = (const float*)d_in[11];
    const float* b0ih = (const float*)d_in[12];
    const float* b0hh = (const float*)d_in[13];
    const float* W1ih = (const float*)d_in[14];
    const float* W1hh = (const float*)d_in[15];
    const float* b1ih = (const float*)d_in[16];
    const float* b1hh = (const float*)d_in[17];
    const float* outW = (const float*)d_in[18];
    const float* outb = (const float*)d_in[19];

    float* out = (float*)d_out;
    const long long NLP  = (long long)B_ * T_ * V_;
    const long long NHID = 2LL * B_ * H_;
    const long long NATT = (long long)B_ * T_ * S_;
    bool full = (long long)out_size >= NLP + NHID + NATT;
    float* lp   = out;
    float* hid  = full ? out + NLP : nullptr;
    float* attn = full ? out + NLP + NHID : nullptr;

    k_init<<<128, 256>>>(ehid);
    k_ukeys<<<256, 256>>>(enc, Ua, bua);

    for (int t = 0; t < T_; t++) {
        int p = t & 1;
        k_pre3sw<<<256, 256>>>(Wa, W0hh, W1hh, lp, t);   // q+gh0+gh1 || smwrite(t-1)
        k_attn<<<32, 512>>>(enc, ba, Va, bva, attn, t);  // scores+softmax+context
        k_gi0<<<96, 256>>>(W0ih, emb);
        k_gi1c0<<<48, 256>>>(W1ih, b0ih, b0hh, p);       // comb0 (fast) + gi1
        k_comb1<<<64, 256>>>(p, b1ih, b1hh);
        k_logits<<<250, 128>>>(outW, outb, p ^ 1);
    }
    k_last<<<128, 256>>>(lp, hid);
}

// round 11
// speedup vs baseline: 1.4742x; 1.4742x over previous
#include <cuda_runtime.h>

#define B_  32
#define S_  64
#define T_  32
#define H_  512
#define V_  32000
#define K3  1536
#define NLT 250   // logits tiles (128 v-rows each)

typedef unsigned long long ull;

// ---------------- device scratch ----------------
__device__ float g_Ukeys[B_ * S_ * H_];
__device__ float g_query[2][1024 * B_];   // [(l*512+h)][b], double buffered
__device__ float g_ctxT[512 * B_];        // context [h][b]
__device__ float g_qpT[4][B_ * H_];       // q partials transposed [b][h]
__device__ float g_gh0p[2][K3 * B_];
__device__ float g_gh1p[2][K3 * B_];
__device__ float g_gi0p[4][K3 * B_];
__device__ float g_gi1p[2][K3 * B_];
__device__ float g_logits[B_ * V_];       // [b][v]
__device__ float g_pm[B_ * NLT];
__device__ float g_ps[B_ * NLT];
__device__ int   g_pi[B_ * NLT];
__device__ int   g_tok[B_];

// ---------------- helpers ----------------
__device__ __forceinline__ ull pk2(float a, float b) {
    ull r; asm("mov.b64 %0, {%1,%2};" : "=l"(r) : "f"(a), "f"(b)); return r;
}
__device__ __forceinline__ ull fma2(ull a, ull b, ull c) {
    ull d; asm("fma.rn.f32x2 %0, %1, %2, %3;" : "=l"(d) : "l"(a), "l"(b), "l"(c)); return d;
}
__device__ __forceinline__ void upk(ull v, float& lo, float& hi) {
    asm("mov.b64 {%0,%1}, %2;" : "=f"(lo), "=f"(hi) : "l"(v));
}
__device__ __forceinline__ float tanh_ap(float x) {
    float y; asm("tanh.approx.f32 %0, %1;" : "=f"(y) : "f"(x)); return y;
}
// streaming 32B load: don't displace the resident L2 set (v8.b32 required for evict_first)
__device__ __forceinline__ void ldg_ef8(const float* p, float* w) {
    asm volatile("ld.global.nc.L2::evict_first.v8.b32 {%0,%1,%2,%3,%4,%5,%6,%7}, [%8];"
        : "=f"(w[0]), "=f"(w[1]), "=f"(w[2]), "=f"(w[3]),
          "=f"(w[4]), "=f"(w[5]), "=f"(w[6]), "=f"(w[7])
        : "l"(p));
}

// ---------------- staging ----------------
__device__ __forceinline__ void stage256(const float* __restrict__ X, float* Xs) {
    int tid = threadIdx.x;
    const float4* s = (const float4*)X;
    float4* d = (float4*)Xs;
    #pragma unroll
    for (int i = 0; i < 8; i++) d[tid + 256 * i] = s[tid + 256 * i];
}
__device__ __forceinline__ void stage128(const float* __restrict__ X, float* Xs) {
    int tid = threadIdx.x;
    const float4* s = (const float4*)X;
    float4* d = (float4*)Xs;
    #pragma unroll
    for (int i = 0; i < 16; i++) d[tid + 128 * i] = s[tid + 128 * i];
}

// ---------------- GEMM tile: 64 m x 32 b x 256 k, 256 threads ----------------
__device__ __forceinline__ void gemm64(
    const float* __restrict__ W, int ldW,
    float* __restrict__ C, int m0, const float* Xs)
{
    int tid = threadIdx.x;
    int bt = tid & 3, mtt = tid >> 2;
    int b0 = bt * 8;
    const float* wr = W + (size_t)(m0 + mtt) * ldW;
    ull acc[4] = {0ULL, 0ULL, 0ULL, 0ULL};
    for (int kk = 0; kk < 256; kk += 4) {
        float4 w = *(const float4*)(wr + kk);
        float wf[4] = {w.x, w.y, w.z, w.w};
        #pragma unroll
        for (int c = 0; c < 4; c++) {
            ull wd = pk2(wf[c], wf[c]);
            #pragma unroll
            for (int j = 0; j < 4; j++)
                acc[j] = fma2(wd, *(const ull*)&Xs[(kk + c) * 32 + b0 + 2 * j], acc[j]);
        }
    }
    #pragma unroll
    for (int j = 0; j < 4; j++)
        *(ull*)&C[(size_t)(m0 + mtt) * 32 + b0 + 2 * j] = acc[j];
}

// transposed-store variant (for q): C[b*512 + m]
__device__ __forceinline__ void gemm64T(
    const float* __restrict__ W, int ldW,
    float* __restrict__ C, int m0, const float* Xs)
{
    int tid = threadIdx.x;
    int bt = tid & 3, mtt = tid >> 2;
    int b0 = bt * 8;
    const float* wr = W + (size_t)(m0 + mtt) * ldW;
    ull acc[4] = {0ULL, 0ULL, 0ULL, 0ULL};
    for (int kk = 0; kk < 256; kk += 4) {
        float4 w = *(const float4*)(wr + kk);
        float wf[4] = {w.x, w.y, w.z, w.w};
        #pragma unroll
        for (int c = 0; c < 4; c++) {
            ull wd = pk2(wf[c], wf[c]);
            #pragma unroll
            for (int j = 0; j < 4; j++)
                acc[j] = fma2(wd, *(const ull*)&Xs[(kk + c) * 32 + b0 + 2 * j], acc[j]);
        }
    }
    int m = m0 + mtt;
    #pragma unroll
    for (int j = 0; j < 4; j++) {
        float lo, hi; upk(acc[j], lo, hi);
        C[(size_t)(b0 + 2 * j) * 512 + m]     = lo;
        C[(size_t)(b0 + 2 * j + 1) * 512 + m] = hi;
    }
}

// ---------------- GEMM tile: 128 m x 32 b x 256 k, 128 threads ----------------
__device__ __forceinline__ void gemm_core(
    const float* __restrict__ W, int ldW,
    float* __restrict__ C, int m0, const float* Xs)
{
    int tid = threadIdx.x;
    int bt = tid & 3, mt = tid >> 2;
    int b0 = bt * 8;
    const float* wr0 = W + (size_t)(m0 + mt) * ldW;

    ull acc[4][4];
    #pragma unroll
    for (int i = 0; i < 4; i++)
        #pragma unroll
        for (int j = 0; j < 4; j++) acc[i][j] = 0ULL;

    for (int kk = 0; kk < 256; kk += 4) {
        float4 w[4];
        #pragma unroll
        for (int i = 0; i < 4; i++)
            w[i] = *(const float4*)(wr0 + (size_t)i * 32 * ldW + kk);
        #pragma unroll
        for (int c = 0; c < 4; c++) {
            ull xp[4];
            #pragma unroll
            for (int j = 0; j < 4; j++)
                xp[j] = *(const ull*)&Xs[(kk + c) * 32 + b0 + 2 * j];
            #pragma unroll
            for (int i = 0; i < 4; i++) {
                const float* wf = reinterpret_cast<const float*>(&w[i]);
                ull wd = pk2(wf[c], wf[c]);
                #pragma unroll
                for (int j = 0; j < 4; j++) acc[i][j] = fma2(wd, xp[j], acc[i][j]);
            }
        }
    }
    #pragma unroll
    for (int i = 0; i < 4; i++)
        #pragma unroll
        for (int j = 0; j < 4; j++)
            *(ull*)&C[(size_t)(m0 + mt + i * 32) * 32 + b0 + 2 * j] = acc[i][j];
}

// ---------------- smwrite unit ----------------
__device__ __forceinline__ void smwrite_unit(int u, float* __restrict__ lp, int tprev,
                                             float* rm, float* rs, int* ri)
{
    int tid = threadIdx.x;
    int b = u >> 2, c = u & 3;
    float m = -1e30f, s = 0.f; int id = 0x7fffffff;
    if (tid < NLT) { m = g_pm[b * NLT + tid]; s = g_ps[b * NLT + tid]; id = g_pi[b * NLT + tid]; }
    rm[tid] = m; rs[tid] = s; ri[tid] = id;
    __syncthreads();
    for (int o = 128; o; o >>= 1) {
        if (tid < o) {
            float mq = rm[tid + o], sq = rs[tid + o];
            int iq = ri[tid + o];
            float mm = rm[tid];
            if (mq > mm || (mq == mm && iq < ri[tid])) {
                rs[tid] = rs[tid] * __expf(mm - mq) + sq; rm[tid] = mq; ri[tid] = iq;
            } else {
                rs[tid] += sq * __expf(mq - mm);
            }
        }
        __syncthreads();
    }
    float lse = logf(rs[0]) + rm[0];
    if (c == 0 && tid == 0) g_tok[b] = ri[0];
    const float* lg = g_logits + (size_t)b * V_;
    float* o = lp + ((size_t)b * T_ + tprev) * V_;
    for (int v = c * 8000 + tid; v < (c + 1) * 8000; v += 256)
        o[v] = lg[v] - lse;
}

// ---------------- init ----------------
__global__ void k_init(const float* __restrict__ ehid) {
    int idx = blockIdx.x * 256 + threadIdx.x;   // 32768
    int row = idx >> 5, b = idx & 31;
    int l = row >> 9, h = row & 511;
    g_query[0][row * 32 + b] = ehid[((size_t)l * 32 + b) * 512 + h];
    if (idx < B_) g_tok[idx] = 1;  // BOS
}

// ---------------- Ukeys = enc @ Ua^T + bua ----------------
__global__ __launch_bounds__(256) void k_ukeys(
    const float* __restrict__ enc, const float* __restrict__ Ua,
    const float* __restrict__ bua)
{
    __shared__ float es[8 * 512];
    int row0 = blockIdx.x * 8;   // grid 256
    int tid = threadIdx.x;
    {
        const float4* src = (const float4*)(enc + (size_t)row0 * 512);
        #pragma unroll
        for (int i = 0; i < 4; i++) ((float4*)es)[tid + 256 * i] = src[tid + 256 * i];
    }
    __syncthreads();
    int h = tid;
    float acc0[8], acc1[8];
    #pragma unroll
    for (int r = 0; r < 8; r++) { acc0[r] = 0.f; acc1[r] = 0.f; }
    const float* u0 = Ua + (size_t)h * 512;
    const float* u1 = Ua + (size_t)(h + 256) * 512;
    for (int k = 0; k < 512; k++) {
        float w0 = u0[k], w1 = u1[k];
        #pragma unroll
        for (int r = 0; r < 8; r++) {
            float x = es[r * 512 + k];
            acc0[r] += w0 * x; acc1[r] += w1 * x;
        }
    }
    float bb0 = bua[h], bb1 = bua[h + 256];
    #pragma unroll
    for (int r = 0; r < 8; r++) {
        g_Ukeys[(size_t)(row0 + r) * 512 + h]       = acc0[r] + bb0;
        g_Ukeys[(size_t)(row0 + r) * 512 + h + 256] = acc1[r] + bb1;
    }
}

// ---------------- N1: pre3 GEMMs (blocks 0..127) + smwrite(t-1) (blocks 128..255) ----------------
__global__ __launch_bounds__(256) void k_pre3sw(
    const float* __restrict__ Wa, const float* __restrict__ Whh0,
    const float* __restrict__ Whh1, float* __restrict__ lp, int t)
{
    __shared__ float Xs[8192];
    int blk = blockIdx.x;
    int par = t & 1;
    const float* hprev = (const float*)g_query[par];
    if (blk < 32) {                 // q: 8 mt x 4 ks, transposed store
        int mt = blk >> 2, ks = blk & 3;
        stage256(hprev + ks * 8192, Xs);
        __syncthreads();
        gemm64T(Wa + ks * 256, 1024, g_qpT[ks], mt * 64, Xs);
    } else if (blk < 80) {          // gh0: 24 mt x 2 ks
        int tt = blk - 32; int mt = tt >> 1, ks = tt & 1;
        stage256(hprev + ks * 8192, Xs);
        __syncthreads();
        gemm64(Whh0 + ks * 256, 512, g_gh0p[ks], mt * 64, Xs);
    } else if (blk < 128) {         // gh1: 24 mt x 2 ks
        int tt = blk - 80; int mt = tt >> 1, ks = tt & 1;
        stage256(hprev + 512 * 32 + ks * 8192, Xs);
        __syncthreads();
        gemm64(Whh1 + ks * 256, 512, g_gh1p[ks], mt * 64, Xs);
    } else if (t > 0) {             // smwrite for step t-1
        smwrite_unit(blk - 128, lp, t - 1, Xs, Xs + 256, (int*)(Xs + 512));
    }
}

// ---------------- N2: attention fused (32 blocks x 512 threads) — R8 proven ----------------
__global__ __launch_bounds__(512) void k_attn(
    const float* __restrict__ enc,
    const float* __restrict__ ba, const float* __restrict__ Va,
    const float* __restrict__ bva,
    float* __restrict__ attn, int t)
{
    __shared__ float qs[512], vas[512], sc[64], ws[64];
    int b = blockIdx.x, tid = threadIdx.x;
    {
        int i = tid;
        qs[i] = g_qpT[0][b * 512 + i] + g_qpT[1][b * 512 + i]
              + g_qpT[2][b * 512 + i] + g_qpT[3][b * 512 + i] + ba[i];
        vas[i] = Va[i];
    }
    __syncthreads();
    int w = tid >> 5, lane = tid & 31;
    #pragma unroll
    for (int si = 0; si < 4; si++) {
        int s = w * 4 + si;
        const float* uk = g_Ukeys + ((size_t)(b * 64 + s)) * 512;
        float acc = 0.f;
        for (int h = lane; h < 512; h += 32)
            acc += vas[h] * tanh_ap(qs[h] + uk[h]);
        #pragma unroll
        for (int o = 16; o; o >>= 1) acc += __shfl_xor_sync(0xffffffffu, acc, o);
        if (lane == 0) sc[s] = acc + bva[0];
    }
    __syncthreads();
    if (tid < 32) {
        float v0 = sc[tid], v1 = sc[32 + tid];
        float m = fmaxf(v0, v1);
        #pragma unroll
        for (int o = 16; o; o >>= 1) m = fmaxf(m, __shfl_xor_sync(0xffffffffu, m, o));
        float e0 = __expf(v0 - m), e1 = __expf(v1 - m);
        float s = e0 + e1;
        #pragma unroll
        for (int o = 16; o; o >>= 1) s += __shfl_xor_sync(0xffffffffu, s, o);
        float inv = 1.f / s;
        ws[tid] = e0 * inv; ws[32 + tid] = e1 * inv;
    }
    __syncthreads();
    if (attn && tid < 64)
        attn[((size_t)b * T_ + t) * 64 + tid] = ws[tid];
    {
        int h = tid;
        float c = 0.f;
        const float* e = enc + ((size_t)b * 64) * 512 + h;
        #pragma unroll 8
        for (int s = 0; s < 64; s++) c += ws[s] * e[(size_t)s * 512];
        g_ctxT[h * 32 + b] = c;
    }
}

// ---------------- N3: gi0 = W0ih @ [emb(tok); ctx]  (96 blocks x 256) ----------------
__global__ __launch_bounds__(256) void k_gi0(
    const float* __restrict__ W0ih, const float* __restrict__ emb)
{
    __shared__ float Xs[8192];
    int blk = blockIdx.x, tid = threadIdx.x;
    int mt = blk >> 2, ks = blk & 3;
    if (ks < 2) {
        int b = tid & 31, seg = tid >> 5;   // 8 segs x 32 k
        int tok = g_tok[b];
        const float* er = emb + (size_t)tok * 512 + ks * 256 + seg * 32;
        #pragma unroll
        for (int i = 0; i < 8; i++) {
            float4 v = *(const float4*)(er + i * 4);
            int k = seg * 32 + i * 4;
            Xs[(k + 0) * 32 + b] = v.x; Xs[(k + 1) * 32 + b] = v.y;
            Xs[(k + 2) * 32 + b] = v.z; Xs[(k + 3) * 32 + b] = v.w;
        }
    } else {
        stage256(g_ctxT + (ks - 2) * 8192, Xs);
    }
    __syncthreads();
    gemm64(W0ih + ks * 256, 1024, g_gi0p[ks], mt * 64, Xs);
}

// ---------------- N4/N6: GRU gate combine (64 blocks x 256, R5/R8 proven) ----------------
__global__ __launch_bounds__(256) void k_comb(
    int layer, int par, const float* __restrict__ bih, const float* __restrict__ bhh)
{
    int idx = blockIdx.x * 256 + threadIdx.x;   // 16384
    int j = idx >> 5, b = idx & 31;
    int o_r = j * 32 + b, o_z = (j + 512) * 32 + b, o_n = (j + 1024) * 32 + b;
    float gir, giz, gin_, ghr, ghz, ghn, hp;
    if (layer == 0) {
        gir  = g_gi0p[0][o_r] + g_gi0p[1][o_r] + g_gi0p[2][o_r] + g_gi0p[3][o_r];
        giz  = g_gi0p[0][o_z] + g_gi0p[1][o_z] + g_gi0p[2][o_z] + g_gi0p[3][o_z];
        gin_ = g_gi0p[0][o_n] + g_gi0p[1][o_n] + g_gi0p[2][o_n] + g_gi0p[3][o_n];
        ghr = g_gh0p[0][o_r] + g_gh0p[1][o_r];
        ghz = g_gh0p[0][o_z] + g_gh0p[1][o_z];
        ghn = g_gh0p[0][o_n] + g_gh0p[1][o_n];
        hp = g_query[par][j * 32 + b];
    } else {
        gir  = g_gi1p[0][o_r] + g_gi1p[1][o_r];
        giz  = g_gi1p[0][o_z] + g_gi1p[1][o_z];
        gin_ = g_gi1p[0][o_n] + g_gi1p[1][o_n];
        ghr = g_gh1p[0][o_r] + g_gh1p[1][o_r];
        ghz = g_gh1p[0][o_z] + g_gh1p[1][o_z];
        ghn = g_gh1p[0][o_n] + g_gh1p[1][o_n];
        hp = g_query[par][(512 + j) * 32 + b];
    }
    gir += bih[j];         ghr += bhh[j];
    giz += bih[j + 512];   ghz += bhh[j + 512];
    gin_ += bih[j + 1024]; ghn += bhh[j + 1024];
    float r = 1.f / (1.f + expf(-(gir + ghr)));
    float z = 1.f / (1.f + expf(-(giz + ghz)));
    float n = tanhf(gin_ + r * ghn);
    float h = (1.f - z) * n + z * hp;
    int off = layer ? 512 : 0;
    g_query[par ^ 1][(off + j) * 32 + b] = h;
}

// ---------------- N5: gi1 = W1ih @ h0 (24 blocks x 128, R5/R8 proven) ----------------
__global__ __launch_bounds__(128) void k_gi1(const float* __restrict__ W1ih, int par1)
{
    __shared__ float Xs[8192];
    int mt = blockIdx.x >> 1, ks = blockIdx.x & 1;   // grid 24
    stage128((const float*)g_query[par1] + ks * 8192, Xs);
    __syncthreads();
    gemm_core(W1ih + ks * 256, 512, g_gi1p[ks], mt * 128, Xs);
}

// ---------------- N7: logits + softmax partials (250 blocks x 128) ----------------
// outW loaded with 32B L2 evict_first so the 65MB stream doesn't flush the hot set.
__global__ __launch_bounds__(128) void k_logits(
    const float* __restrict__ outW, const float* __restrict__ outb, int parN)
{
    __shared__ float Xs[8192];
    int tid = threadIdx.x;
    int bt = tid & 3, mt = tid >> 2;
    int b0 = bt * 8;
    int v0 = blockIdx.x * 128;   // grid 250
    ull acc[4][4];
    #pragma unroll
    for (int i = 0; i < 4; i++)
        #pragma unroll
        for (int j = 0; j < 4; j++) acc[i][j] = 0ULL;

    const float* h1T = (const float*)g_query[parN] + 512 * 32;
    for (int ck = 0; ck < 2; ck++) {
        if (ck) __syncthreads();
        stage128(h1T + ck * 8192, Xs);
        __syncthreads();
        const float* wr0 = outW + (size_t)(v0 + mt) * 512 + ck * 256;
        for (int kk = 0; kk < 256; kk += 8) {
            float w[4][8];
            #pragma unroll
            for (int i = 0; i < 4; i++)
                ldg_ef8(wr0 + (size_t)i * 32 * 512 + kk, w[i]);
            #pragma unroll
            for (int c = 0; c < 8; c++) {
                ull xp[4];
                #pragma unroll
                for (int j = 0; j < 4; j++)
                    xp[j] = *(const ull*)&Xs[(kk + c) * 32 + b0 + 2 * j];
                #pragma unroll
                for (int i = 0; i < 4; i++) {
                    ull wd = pk2(w[i][c], w[i][c]);
                    #pragma unroll
                    for (int j = 0; j < 4; j++) acc[i][j] = fma2(wd, xp[j], acc[i][j]);
                }
            }
        }
    }
    float lv[8][4];
    #pragma unroll
    for (int i = 0; i < 4; i++) {
        int v = v0 + mt + i * 32;
        float bb = outb[v];
        #pragma unroll
        for (int j = 0; j < 4; j++) {
            float lo, hi; upk(acc[i][j], lo, hi);
            lv[2 * j][i] = lo + bb; lv[2 * j + 1][i] = hi + bb;
            g_logits[(size_t)(b0 + 2 * j) * V_ + v]     = lo + bb;
            g_logits[(size_t)(b0 + 2 * j + 1) * V_ + v] = hi + bb;
        }
    }
    __syncthreads();
    float* sm_m = Xs;
    float* sm_s = Xs + 1024;
    int*   sm_i = (int*)(Xs + 2048);
    #pragma unroll
    for (int jj = 0; jj < 8; jj++) {
        int b = b0 + jj;
        float m = lv[jj][0]; int id = v0 + mt;
        #pragma unroll
        for (int i = 1; i < 4; i++) {
            float x = lv[jj][i];
            if (x > m) { m = x; id = v0 + mt + i * 32; }
        }
        float s = 0.f;
        #pragma unroll
        for (int i = 0; i < 4; i++) s += __expf(lv[jj][i] - m);
        sm_m[b * 32 + mt] = m; sm_s[b * 32 + mt] = s; sm_i[b * 32 + mt] = id;
    }
    __syncthreads();
    if (tid < 32) {
        int b = tid;
        float m = sm_m[b * 32], s = sm_s[b * 32];
        int id = sm_i[b * 32];
        for (int q = 1; q < 32; q++) {
            float mq = sm_m[b * 32 + q], sq = sm_s[b * 32 + q];
            int iq = sm_i[b * 32 + q];
            if (mq > m || (mq == m && iq < id)) {
                s = s * __expf(m - mq) + sq; m = mq; id = iq;
            } else {
                s += sq * __expf(mq - m);
            }
        }
        g_pm[b * NLT + blockIdx.x] = m;
        g_ps[b * NLT + blockIdx.x] = s;
        g_pi[b * NLT + blockIdx.x] = id;
    }
}

// ---------------- trailing: smwrite(31) + hidden out (128 blocks) ----------------
__global__ __launch_bounds__(256) void k_last(float* __restrict__ lp, float* __restrict__ hid)
{
    __shared__ float rm[256], rs[256];
    __shared__ int ri[256];
    smwrite_unit(blockIdx.x, lp, T_ - 1, rm, rs, ri);
    int idx = blockIdx.x * 256 + threadIdx.x;   // 32768
    int row = idx >> 5, b = idx & 31;
    int l = row >> 9, h = row & 511;
    if (hid) hid[((size_t)l * 32 + b) * 512 + h] = g_query[0][row * 32 + b];
}

// ---------------- launcher (single stream) ----------------
extern "C" void kernel_launch(void* const* d_in, const int* in_sizes, int n_in,
                              void* d_out, int out_size)
{
    const float* enc  = (const float*)d_in[0];
    const float* ehid = (const float*)d_in[1];
    const float* emb  = (const float*)d_in[3];
    const float* Wa   = (const float*)d_in[4];
    const float* ba   = (const float*)d_in[5];
    const float* Ua   = (const float*)d_in[6];
    const float* bua  = (const float*)d_in[7];
    const float* Va   = (const float*)d_in[8];
    const float* bva  = (const float*)d_in[9];
    const float* W0ih = (const float*)d_in[10];
    const float* W0hh = (const float*)d_in[11];
    const float* b0ih = (const float*)d_in[12];
    const float* b0hh = (const float*)d_in[13];
    const float* W1ih = (const float*)d_in[14];
    const float* W1hh = (const float*)d_in[15];
    const float* b1ih = (const float*)d_in[16];
    const float* b1hh = (const float*)d_in[17];
    const float* outW = (const float*)d_in[18];
    const float* outb = (const float*)d_in[19];

    float* out = (float*)d_out;
    const long long NLP  = (long long)B_ * T_ * V_;
    const long long NHID = 2LL * B_ * H_;
    const long long NATT = (long long)B_ * T_ * S_;
    bool full = (long long)out_size >= NLP + NHID + NATT;
    float* lp   = out;
    float* hid  = full ? out + NLP : nullptr;
    float* attn = full ? out + NLP + NHID : nullptr;

    k_init<<<128, 256>>>(ehid);
    k_ukeys<<<256, 256>>>(enc, Ua, bua);

    for (int t = 0; t < T_; t++) {
        int p = t & 1;
        k_pre3sw<<<256, 256>>>(Wa, W0hh, W1hh, lp, t);   // q+gh0+gh1 || smwrite(t-1)
        k_attn<<<32, 512>>>(enc, ba, Va, bva, attn, t);  // scores+softmax+context
        k_gi0<<<96, 256>>>(W0ih, emb);
        k_comb<<<64, 256>>>(0, p, b0ih, b0hh);
        k_gi1<<<24, 128>>>(W1ih, p ^ 1);
        k_comb<<<64, 256>>>(1, p, b1ih, b1hh);
        k_logits<<<250, 128>>>(outW, outb, p ^ 1);
    }
    k_last<<<128, 256>>>(lp, hid);
}